// round 14
// baseline (speedup 1.0000x reference)
#include <cuda_runtime.h>
#include <cuda_fp16.h>

#define NA 16       // agents
#define ND 256      // action dim (K of the GEMM)
#define NN 64       // K_kernels * NA = output cols (N of the GEMM)
#define MT 128      // rows per tile (8 warps x 16)
#define NTHREADS 256
#define NWARPS 8
#define NSTAGES 5   // per-warp cp.async A stages (1KB each)
#define AHEAD 4     // commit-ahead distance
// wait_group 3: with commits 0..kk+AHEAD at iter kk, group kk+1 is complete
#define GRID 444    // 148 SMs x 3 CTAs: persistent

// dynamic smem layout (bytes)
#define SB_OFF    0                        // B tile fp16: 32KB
#define SA_OFF    32768                    // A ring: 8 warps * 5 stages * 1KB = 40KB
#define SKERN_OFF (32768 + NWARPS*NSTAGES*1024)
#define SBIAS_OFF (SKERN_OFF + 256)
#define SMEM_TOTAL (SBIAS_OFF + 256)       // 74240 -> 3 CTAs/SM

__device__ __forceinline__ unsigned pack_h2(float a, float b) {
    __half2 h = __floats2half2_rn(a, b);
    return *reinterpret_cast<unsigned*>(&h);
}

#define CP_ASYNC_CG16(dst_u32, src_ptr) \
    asm volatile("cp.async.cg.shared.global [%0], [%1], 16;\n" :: "r"(dst_u32), "l"(src_ptr))
#define CP_COMMIT()  asm volatile("cp.async.commit_group;\n" ::: "memory")
#define CP_WAIT3()   asm volatile("cp.async.wait_group 3;\n" ::: "memory")

// ---------------------------------------------------------------------------
// Persistent fused kernel, cross-tile flattened cp.async pipeline with
// one-iteration A-register prefetch: at iter kk the warp loads+packs the
// fragment for iter kk+1, so the MMA block never waits on LDS/pack latency.
// ---------------------------------------------------------------------------
__global__ void __launch_bounds__(NTHREADS, 3)
mixer_kernel(const float* __restrict__ aq,
             const float* __restrict__ acts,
             const float* __restrict__ mq,
             const float* __restrict__ Vp,
             const float* __restrict__ sel,
             const float* __restrict__ keysp,
             const float* __restrict__ si_keys,
             const float* __restrict__ si_agents,
             const float* __restrict__ si_W,
             const float* __restrict__ si_b,
             float* __restrict__ out,
             int Btot, int out_size)
{
    extern __shared__ char smem[];
    __half* sB    = reinterpret_cast<__half*>(smem + SB_OFF);
    float4* sA4   = reinterpret_cast<float4*>(smem + SA_OFF);
    float*  sKern = reinterpret_cast<float*>(smem + SKERN_OFF);
    float*  sBias = reinterpret_cast<float*>(smem + SBIAS_OFF);

    const int tid = threadIdx.x;

    // kern[n] = (|si_keys[k]|+1e-10) * sigmoid(si_agents[k][a]); bias[n] = si_b
    if (tid < NN) {
        int k = tid >> 4;
        float sg = 1.0f / (1.0f + __expf(-si_agents[tid]));
        sKern[tid] = (fabsf(si_keys[k]) + 1e-10f) * sg;
        sBias[tid] = si_b[tid];
    }

    // scalar tail outputs (one thread of one CTA)
    if (blockIdx.x == 0 && tid == NTHREADS - 1 && out_size >= Btot + 5) {
        float ssq = 0.f;
        for (int h = 0; h < 4; ++h) {
            float d = 0.f;
            for (int e = 0; e < 64; ++e) d = fmaf(sel[h * 64 + e], keysp[h * 64 + e], d);
            ssq += d * d;
        }
        out[Btot] = 0.001f * ssq;                  // attend_mag_regs
        float aw = 0.0625f;                         // softmax of equal logits
        float ent = -16.0f * (logf(aw + 1e-8f) * aw);
        for (int h = 0; h < 4; ++h) out[Btot + 1 + h] = ent;  // head_entropies
    }

    // Stage B ONCE from si_W: K-permutation fused into packing.
    // dest seg(2blk) = xy-halves of 4 float4s, seg(2blk+1) = zw-halves.
    // Swizzle: seg' = seg ^ (r & 7); 16B segments.
    for (int s = tid; s < 64 * 16; s += NTHREADS) {
        int r = s >> 4, blk = s & 15;
        const float4* src = reinterpret_cast<const float4*>(si_W + r * ND + blk * 16);
        float4 f0 = src[0], f1 = src[1], f2 = src[2], f3 = src[3];
        uint4 seg0, seg1;
        seg0.x = pack_h2(f0.x, f0.y); seg0.y = pack_h2(f1.x, f1.y);
        seg0.z = pack_h2(f2.x, f2.y); seg0.w = pack_h2(f3.x, f3.y);
        seg1.x = pack_h2(f0.z, f0.w); seg1.y = pack_h2(f1.z, f1.w);
        seg1.z = pack_h2(f2.z, f2.w); seg1.w = pack_h2(f3.z, f3.w);
        int c0 = 2 * blk, c1 = 2 * blk + 1;
        *reinterpret_cast<uint4*>(sB + r * ND + ((c0 ^ (r & 7)) << 3)) = seg0;
        *reinterpret_cast<uint4*>(sB + r * ND + ((c1 ^ (r & 7)) << 3)) = seg1;
    }
    __syncthreads();

    // warp-constant geometry
    const int w = tid >> 5, l = tid & 31;
    const int quad = l >> 2, qid = l & 3;
    const int l7 = l & 7, t8 = l >> 3;
    const int cA = qid * 2;
    const int ldRowA = l >> 2;            // cp.async: lane l owns segs l, l+32
    const int ldC4A  = l & 3;

    const unsigned sAaddr = (unsigned)__cvta_generic_to_shared(sA4) + (unsigned)(w * NSTAGES * 1024);
    const unsigned sBaddr = (unsigned)__cvta_generic_to_shared(sB);
    const unsigned segOff0 = (unsigned)((ldRowA * 4 + ldC4A) * 16);
    const unsigned segOff1 = segOff0 + 8 * 4 * 16;
    const int rowB_off = (t8 >> 1) * 8 + l7;   // ldmatrix lane geometry
    const int s0B = t8 & 1;
    // consume offsets within a stage (lane-private float4s #l and #(l+32))
    const int rdOff0 = quad * 4 + qid;
    const int rdOff1 = (quad + 8) * 4 + qid;
    const float4* sAw = sA4 + w * NSTAGES * 64;   // this warp's ring base

    const float v = Vp[0] * 0.0625f;
    const int ntiles = (Btot + MT - 1) / MT;

    int tile = blockIdx.x;
    if (tile >= ntiles) return;

    // per-tile A pointer computation (clamped)
    const float *gA0, *gA1;
    {
        long wr0 = (long)tile * MT + w * 16;
        long g0 = wr0 + ldRowA;      if (g0 >= Btot) g0 = Btot - 1;
        long g1 = wr0 + 8 + ldRowA;  if (g1 >= Btot) g1 = Btot - 1;
        gA0 = acts + g0 * ND + ldC4A * 4;
        gA1 = acts + g1 * ND + ldC4A * 4;
    }

    int ringOff = 0;   // ring slot of current tile's k-step 0 (global-iter mod 5)

    // prologue: commit groups for k = 0..AHEAD-1 of the first tile
#pragma unroll
    for (int kk = 0; kk < AHEAD; ++kk) {
        unsigned stBase = sAaddr + (unsigned)(kk * 1024);
        CP_ASYNC_CG16(stBase + segOff0, gA0 + kk * 16);
        CP_ASYNC_CG16(stBase + segOff1, gA1 + kk * 16);
        CP_COMMIT();
    }
    // wait for group 0, pre-pack iter-0 fragment
    unsigned a0, a1, a2, a3;
    {
        CP_WAIT3();                      // 4 committed, <=3 outstanding -> g0 done
        float4 f0 = sAw[rdOff0];
        float4 f1 = sAw[rdOff1];
        a0 = pack_h2(f0.x, f0.y);
        a1 = pack_h2(f1.x, f1.y);
        a2 = pack_h2(f0.z, f0.w);
        a3 = pack_h2(f1.z, f1.w);
    }

    while (true) {
        const int nextTile = tile + GRID;
        const bool hasNext = nextTile < ntiles;
        const float *nA0 = gA0, *nA1 = gA1;
        if (hasNext) {
            long wr0 = (long)nextTile * MT + w * 16;
            long g0 = wr0 + ldRowA;      if (g0 >= Btot) g0 = Btot - 1;
            long g1 = wr0 + 8 + ldRowA;  if (g1 >= Btot) g1 = Btot - 1;
            nA0 = acts + g0 * ND + ldC4A * 4;
            nA1 = acts + g1 * ND + ldC4A * 4;
        }

        const long warpRow0 = (long)tile * MT + w * 16;
        long r0 = warpRow0 + quad;
        long r1 = r0 + 8;
        long r0c = (r0 < Btot) ? r0 : (long)(Btot - 1);
        long r1c = (r1 < Btot) ? r1 : (long)(Btot - 1);

        // hoisted adv_q inputs: complete under the mainloop's shadow
        const float* aqr0 = aq + r0c * NA;
        const float* aqr1 = aq + r1c * NA;
        const float* mqr0 = mq + r0c * NA;
        const float* mqr1 = mq + r1c * NA;
        float2 aq0a = __ldcs((const float2*)(aqr0 + cA));
        float2 aq0b = __ldcs((const float2*)(aqr0 + cA + 8));
        float2 aq1a = __ldcs((const float2*)(aqr1 + cA));
        float2 aq1b = __ldcs((const float2*)(aqr1 + cA + 8));
        float2 mq0a = __ldcs((const float2*)(mqr0 + cA));
        float2 mq0b = __ldcs((const float2*)(mqr0 + cA + 8));
        float2 mq1a = __ldcs((const float2*)(mqr1 + cA));
        float2 mq1b = __ldcs((const float2*)(mqr1 + cA + 8));
        float advq[2][4];
        advq[0][0] = fmaf(0.25f, aq0a.x, v) - fmaf(0.25f, mq0a.x, v);
        advq[0][1] = fmaf(0.25f, aq0a.y, v) - fmaf(0.25f, mq0a.y, v);
        advq[0][2] = fmaf(0.25f, aq0b.x, v) - fmaf(0.25f, mq0b.x, v);
        advq[0][3] = fmaf(0.25f, aq0b.y, v) - fmaf(0.25f, mq0b.y, v);
        advq[1][0] = fmaf(0.25f, aq1a.x, v) - fmaf(0.25f, mq1a.x, v);
        advq[1][1] = fmaf(0.25f, aq1a.y, v) - fmaf(0.25f, mq1a.y, v);
        advq[1][2] = fmaf(0.25f, aq1b.x, v) - fmaf(0.25f, mq1b.x, v);
        advq[1][3] = fmaf(0.25f, aq1b.y, v) - fmaf(0.25f, mq1b.y, v);

        float acc[8][4];
#pragma unroll
        for (int i = 0; i < 8; ++i)
#pragma unroll
            for (int j = 0; j < 4; ++j) acc[i][j] = 0.f;

#pragma unroll
        for (int kk = 0; kk < 16; ++kk) {
            // commit group for global iter kk+AHEAD (same tile or next tile)
            {
                int pre = kk + AHEAD;
                int slot = (ringOff + pre) % NSTAGES;
                unsigned stBase = sAaddr + (unsigned)(slot * 1024);
                if (pre < 16) {
                    CP_ASYNC_CG16(stBase + segOff0, gA0 + pre * 16);
                    CP_ASYNC_CG16(stBase + segOff1, gA1 + pre * 16);
                } else {
                    int pk = pre - 16;              // next tile k-steps
                    CP_ASYNC_CG16(stBase + segOff0, nA0 + pk * 16);
                    CP_ASYNC_CG16(stBase + segOff1, nA1 + pk * 16);
                }
            }
            CP_COMMIT();
            CP_WAIT3();       // group (kk+1) complete -> prefetch is safe

            // prefetch + pack fragment for iter kk+1 (possibly next tile's k0)
            int nslot = (ringOff + kk + 1) % NSTAGES;
            const float4* st = sAw + nslot * 64;
            float4 f0 = st[rdOff0];
            float4 f1 = st[rdOff1];
            unsigned na0 = pack_h2(f0.x, f0.y);
            unsigned na1 = pack_h2(f1.x, f1.y);
            unsigned na2 = pack_h2(f0.z, f0.w);
            unsigned na3 = pack_h2(f1.z, f1.w);

            // MMA block for iter kk using pre-packed a0..a3
#pragma unroll
            for (int p = 0; p < 4; ++p) {
                unsigned addrB = sBaddr
                               + (unsigned)((p * 16 + rowB_off) * (ND * 2))
                               + (unsigned)(((kk * 2 + s0B) ^ l7) << 4);
                unsigned b0, b1, b2, b3;
                asm volatile("ldmatrix.sync.aligned.m8n8.x4.shared.b16 {%0,%1,%2,%3}, [%4];\n"
                             : "=r"(b0), "=r"(b1), "=r"(b2), "=r"(b3) : "r"(addrB));
                asm volatile("mma.sync.aligned.m16n8k16.row.col.f32.f16.f16.f32 "
                             "{%0,%1,%2,%3}, {%4,%5,%6,%7}, {%8,%9}, {%0,%1,%2,%3};\n"
                             : "+f"(acc[2*p][0]), "+f"(acc[2*p][1]),
                               "+f"(acc[2*p][2]), "+f"(acc[2*p][3])
                             : "r"(a0), "r"(a1), "r"(a2), "r"(a3), "r"(b0), "r"(b1));
                asm volatile("mma.sync.aligned.m16n8k16.row.col.f32.f16.f16.f32 "
                             "{%0,%1,%2,%3}, {%4,%5,%6,%7}, {%8,%9}, {%0,%1,%2,%3};\n"
                             : "+f"(acc[2*p+1][0]), "+f"(acc[2*p+1][1]),
                               "+f"(acc[2*p+1][2]), "+f"(acc[2*p+1][3])
                             : "r"(a0), "r"(a1), "r"(a2), "r"(a3), "r"(b2), "r"(b3));
            }
            a0 = na0; a1 = na1; a2 = na2; a3 = na3;
        }

        // Epilogue. acc[nt][h*2+j] = row (r0 + h*8), col n = nt*8 + cA + j.
        float partial[2] = {0.f, 0.f};
#pragma unroll
        for (int h = 0; h < 2; ++h) {
#pragma unroll
            for (int j = 0; j < 2; ++j) {
#pragma unroll
                for (int pp = 0; pp < 2; ++pp) {
                    float s = 0.f;
#pragma unroll
                    for (int q = 0; q < 4; ++q) {
                        int nt = 2 * q + pp;
                        int n = nt * 8 + cA + j;
                        float x = acc[nt][h * 2 + j] + sBias[n];
                        x = 1.0f / (1.0f + __expf(-x));
                        s = fmaf(x, sKern[n], s);
                    }
                    partial[h] += advq[h][pp * 2 + j] * (s - 1.0f);
                }
            }
        }
        partial[0] += __shfl_xor_sync(0xffffffffu, partial[0], 1);
        partial[0] += __shfl_xor_sync(0xffffffffu, partial[0], 2);
        partial[1] += __shfl_xor_sync(0xffffffffu, partial[1], 1);
        partial[1] += __shfl_xor_sync(0xffffffffu, partial[1], 2);
        if (qid == 0) {
            if (r0 < Btot) out[r0] = partial[0];
            if (r1 < Btot) out[r1] = partial[1];
        }

        if (!hasNext) break;
        tile = nextTile;
        gA0 = nA0; gA1 = nA1;
        ringOff += 1;                         // 16 mod 5
        if (ringOff >= NSTAGES) ringOff -= NSTAGES;
    }
}

// ---------------------------------------------------------------------------
extern "C" void kernel_launch(void* const* d_in, const int* in_sizes, int n_in,
                              void* d_out, int out_size)
{
    const float* agent_qs  = (const float*)d_in[0];
    const float* actions   = (const float*)d_in[1];
    const float* max_q_i   = (const float*)d_in[2];
    const float* selectors = (const float*)d_in[3];
    const float* keys      = (const float*)d_in[4];
    const float* V         = (const float*)d_in[5];
    const float* si_keys   = (const float*)d_in[6];
    const float* si_agents = (const float*)d_in[7];
    const float* si_W      = (const float*)d_in[8];
    const float* si_b      = (const float*)d_in[9];
    float* out = (float*)d_out;

    int Btot = in_sizes[0] / NA;   // B0*T

    cudaFuncSetAttribute(mixer_kernel,
                         cudaFuncAttributeMaxDynamicSharedMemorySize, SMEM_TOTAL);

    int ntiles = (Btot + MT - 1) / MT;
    int grid = ntiles < GRID ? ntiles : GRID;
    mixer_kernel<<<grid, NTHREADS, SMEM_TOTAL>>>(agent_qs, actions, max_q_i, V,
                                                 selectors, keys,
                                                 si_keys, si_agents, si_W, si_b,
                                                 out, Btot, out_size);
}

// round 16
// speedup vs baseline: 1.0762x; 1.0762x over previous
#include <cuda_runtime.h>
#include <cuda_fp16.h>

#define NA 16       // agents
#define ND 256      // action dim (K of the GEMM)
#define NN 64       // K_kernels * NA = output cols (N of the GEMM)
#define MT 128      // rows per tile (8 warps x 16)
#define NTHREADS 256
#define NWARPS 8
#define NSTAGES 5   // per-warp cp.async A stages (1KB each)
#define PIPE_D 4    // wait_group depth (max WAR-safe with 5 stages)
#define GRID 444    // 148 SMs x 3 CTAs: persistent

// dynamic smem layout (bytes)
#define SB_OFF    0                        // B tile fp16: 32KB
#define SA_OFF    32768                    // A ring: 8 warps * 5 stages * 1KB = 40KB
#define SKERN_OFF (32768 + NWARPS*NSTAGES*1024)
#define SBIAS_OFF (SKERN_OFF + 256)
#define SMEM_TOTAL (SBIAS_OFF + 256)       // 74240 -> 3 CTAs/SM

__device__ __forceinline__ unsigned pack_h2(float a, float b) {
    __half2 h = __floats2half2_rn(a, b);
    return *reinterpret_cast<unsigned*>(&h);
}

#define CP_ASYNC_CG16(dst_u32, src_ptr) \
    asm volatile("cp.async.cg.shared.global [%0], [%1], 16;\n" :: "r"(dst_u32), "l"(src_ptr))
#define CP_COMMIT()  asm volatile("cp.async.commit_group;\n" ::: "memory")
#define CP_WAIT()    asm volatile("cp.async.wait_group %0;\n" :: "n"(PIPE_D) : "memory")

// ---------------------------------------------------------------------------
// Persistent fused kernel, cross-tile flattened cp.async pipeline (R12 base):
// ring slot = (global iter) mod NSTAGES, tracked INCREMENTALLY in two
// registers (no runtime mod). Tail iterations of tile t prefetch the head
// k-steps of tile t+GRID, so the pipe never drains.
// ---------------------------------------------------------------------------
__global__ void __launch_bounds__(NTHREADS, 3)
mixer_kernel(const float* __restrict__ aq,
             const float* __restrict__ acts,
             const float* __restrict__ mq,
             const float* __restrict__ Vp,
             const float* __restrict__ sel,
             const float* __restrict__ keysp,
             const float* __restrict__ si_keys,
             const float* __restrict__ si_agents,
             const float* __restrict__ si_W,
             const float* __restrict__ si_b,
             float* __restrict__ out,
             int Btot, int out_size)
{
    extern __shared__ char smem[];
    __half* sB    = reinterpret_cast<__half*>(smem + SB_OFF);
    float4* sA4   = reinterpret_cast<float4*>(smem + SA_OFF);
    float*  sKern = reinterpret_cast<float*>(smem + SKERN_OFF);
    float*  sBias = reinterpret_cast<float*>(smem + SBIAS_OFF);

    const int tid = threadIdx.x;

    // kern[n] = (|si_keys[k]|+1e-10) * sigmoid(si_agents[k][a]); bias[n] = si_b
    if (tid < NN) {
        int k = tid >> 4;
        float sg = 1.0f / (1.0f + __expf(-si_agents[tid]));
        sKern[tid] = (fabsf(si_keys[k]) + 1e-10f) * sg;
        sBias[tid] = si_b[tid];
    }

    // scalar tail outputs (one thread of one CTA)
    if (blockIdx.x == 0 && tid == NTHREADS - 1 && out_size >= Btot + 5) {
        float ssq = 0.f;
        for (int h = 0; h < 4; ++h) {
            float d = 0.f;
            for (int e = 0; e < 64; ++e) d = fmaf(sel[h * 64 + e], keysp[h * 64 + e], d);
            ssq += d * d;
        }
        out[Btot] = 0.001f * ssq;                  // attend_mag_regs
        float aw = 0.0625f;                         // softmax of equal logits
        float ent = -16.0f * (logf(aw + 1e-8f) * aw);
        for (int h = 0; h < 4; ++h) out[Btot + 1 + h] = ent;  // head_entropies
    }

    // Stage B ONCE from si_W: K-permutation fused into packing.
    // dest seg(2blk) = xy-halves of 4 float4s, seg(2blk+1) = zw-halves.
    // Swizzle: seg' = seg ^ (r & 7); 16B segments.
    for (int s = tid; s < 64 * 16; s += NTHREADS) {
        int r = s >> 4, blk = s & 15;
        const float4* src = reinterpret_cast<const float4*>(si_W + r * ND + blk * 16);
        float4 f0 = src[0], f1 = src[1], f2 = src[2], f3 = src[3];
        uint4 seg0, seg1;
        seg0.x = pack_h2(f0.x, f0.y); seg0.y = pack_h2(f1.x, f1.y);
        seg0.z = pack_h2(f2.x, f2.y); seg0.w = pack_h2(f3.x, f3.y);
        seg1.x = pack_h2(f0.z, f0.w); seg1.y = pack_h2(f1.z, f1.w);
        seg1.z = pack_h2(f2.z, f2.w); seg1.w = pack_h2(f3.z, f3.w);
        int c0 = 2 * blk, c1 = 2 * blk + 1;
        *reinterpret_cast<uint4*>(sB + r * ND + ((c0 ^ (r & 7)) << 3)) = seg0;
        *reinterpret_cast<uint4*>(sB + r * ND + ((c1 ^ (r & 7)) << 3)) = seg1;
    }
    __syncthreads();

    // warp-constant geometry
    const int w = tid >> 5, l = tid & 31;
    const int quad = l >> 2, qid = l & 3;
    const int l7 = l & 7, t8 = l >> 3;
    const int cA = qid * 2;
    const int ldRowA = l >> 2;            // cp.async: lane l owns segs l, l+32
    const int ldC4A  = l & 3;

    const unsigned sAaddr = (unsigned)__cvta_generic_to_shared(sA4) + (unsigned)(w * NSTAGES * 1024);
    const unsigned sBaddr = (unsigned)__cvta_generic_to_shared(sB);
    const unsigned segOff0 = (unsigned)((ldRowA * 4 + ldC4A) * 16);
    const unsigned segOff1 = segOff0 + 8 * 4 * 16;
    const int rowB_off = (t8 >> 1) * 8 + l7;   // ldmatrix lane geometry
    const int s0B = t8 & 1;
    const float4* sAw = sA4 + w * NSTAGES * 64;   // this warp's ring base
    const int rdOff0 = quad * 4 + qid;            // lane-private float4 #l
    const int rdOff1 = (quad + 8) * 4 + qid;      // lane-private float4 #(l+32)

    const float v = Vp[0] * 0.0625f;
    const int ntiles = (Btot + MT - 1) / MT;

    int tile = blockIdx.x;
    if (tile >= ntiles) return;

    // per-tile A pointer computation (clamped)
    const float *gA0, *gA1;
    {
        long wr0 = (long)tile * MT + w * 16;
        long g0 = wr0 + ldRowA;      if (g0 >= Btot) g0 = Btot - 1;
        long g1 = wr0 + 8 + ldRowA;  if (g1 >= Btot) g1 = Btot - 1;
        gA0 = acts + g0 * ND + ldC4A * 4;
        gA1 = acts + g1 * ND + ldC4A * 4;
    }

    // incremental ring-slot registers (global-iter mod 5, never reset)
    int preSlot = PIPE_D;   // slot for the next prefetch (global iter g+PIPE_D)
    int curSlot = 0;        // slot for the current consume (global iter g)

    // prologue: first PIPE_D k-steps of the first tile (slots 0..3)
#pragma unroll
    for (int kk = 0; kk < PIPE_D; ++kk) {
        unsigned stBase = sAaddr + (unsigned)(kk * 1024);
        CP_ASYNC_CG16(stBase + segOff0, gA0 + kk * 16);
        CP_ASYNC_CG16(stBase + segOff1, gA1 + kk * 16);
        CP_COMMIT();
    }

    while (true) {
        const int nextTile = tile + GRID;
        const bool hasNext = nextTile < ntiles;
        const float *nA0 = gA0, *nA1 = gA1;
        if (hasNext) {
            long wr0 = (long)nextTile * MT + w * 16;
            long g0 = wr0 + ldRowA;      if (g0 >= Btot) g0 = Btot - 1;
            long g1 = wr0 + 8 + ldRowA;  if (g1 >= Btot) g1 = Btot - 1;
            nA0 = acts + g0 * ND + ldC4A * 4;
            nA1 = acts + g1 * ND + ldC4A * 4;
        }

        const long warpRow0 = (long)tile * MT + w * 16;
        long r0 = warpRow0 + quad;
        long r1 = r0 + 8;
        long r0c = (r0 < Btot) ? r0 : (long)(Btot - 1);
        long r1c = (r1 < Btot) ? r1 : (long)(Btot - 1);

        // hoisted adv_q inputs: complete under the mainloop's shadow
        const float* aqr0 = aq + r0c * NA;
        const float* aqr1 = aq + r1c * NA;
        const float* mqr0 = mq + r0c * NA;
        const float* mqr1 = mq + r1c * NA;
        float2 aq0a = __ldcs((const float2*)(aqr0 + cA));
        float2 aq0b = __ldcs((const float2*)(aqr0 + cA + 8));
        float2 aq1a = __ldcs((const float2*)(aqr1 + cA));
        float2 aq1b = __ldcs((const float2*)(aqr1 + cA + 8));
        float2 mq0a = __ldcs((const float2*)(mqr0 + cA));
        float2 mq0b = __ldcs((const float2*)(mqr0 + cA + 8));
        float2 mq1a = __ldcs((const float2*)(mqr1 + cA));
        float2 mq1b = __ldcs((const float2*)(mqr1 + cA + 8));
        float advq[2][4];
        advq[0][0] = fmaf(0.25f, aq0a.x, v) - fmaf(0.25f, mq0a.x, v);
        advq[0][1] = fmaf(0.25f, aq0a.y, v) - fmaf(0.25f, mq0a.y, v);
        advq[0][2] = fmaf(0.25f, aq0b.x, v) - fmaf(0.25f, mq0b.x, v);
        advq[0][3] = fmaf(0.25f, aq0b.y, v) - fmaf(0.25f, mq0b.y, v);
        advq[1][0] = fmaf(0.25f, aq1a.x, v) - fmaf(0.25f, mq1a.x, v);
        advq[1][1] = fmaf(0.25f, aq1a.y, v) - fmaf(0.25f, mq1a.y, v);
        advq[1][2] = fmaf(0.25f, aq1b.x, v) - fmaf(0.25f, mq1b.x, v);
        advq[1][3] = fmaf(0.25f, aq1b.y, v) - fmaf(0.25f, mq1b.y, v);

        float acc[8][4];
#pragma unroll
        for (int i = 0; i < 8; ++i)
#pragma unroll
            for (int j = 0; j < 4; ++j) acc[i][j] = 0.f;

#pragma unroll
        for (int kk = 0; kk < 16; ++kk) {
            // prefetch global-iteration (this + PIPE_D): same tile or next tile
            {
                unsigned stBase = sAaddr + (unsigned)(preSlot << 10);
                if (kk + PIPE_D < 16) {
                    CP_ASYNC_CG16(stBase + segOff0, gA0 + (kk + PIPE_D) * 16);
                    CP_ASYNC_CG16(stBase + segOff1, gA1 + (kk + PIPE_D) * 16);
                } else {
                    CP_ASYNC_CG16(stBase + segOff0, nA0 + (kk + PIPE_D - 16) * 16);
                    CP_ASYNC_CG16(stBase + segOff1, nA1 + (kk + PIPE_D - 16) * 16);
                }
            }
            CP_COMMIT();
            CP_WAIT();        // groups <= PIPE_D outstanding -> iter kk complete

            const float4* st = sAw + curSlot * 64;
            float4 f0 = st[rdOff0];
            float4 f1 = st[rdOff1];
            unsigned a0 = pack_h2(f0.x, f0.y);
            unsigned a1 = pack_h2(f1.x, f1.y);
            unsigned a2 = pack_h2(f0.z, f0.w);
            unsigned a3 = pack_h2(f1.z, f1.w);

            // incremental slot advance (replaces runtime mod)
            preSlot = (preSlot == NSTAGES - 1) ? 0 : preSlot + 1;
            curSlot = (curSlot == NSTAGES - 1) ? 0 : curSlot + 1;

#pragma unroll
            for (int p = 0; p < 4; ++p) {
                unsigned addrB = sBaddr
                               + (unsigned)((p * 16 + rowB_off) * (ND * 2))
                               + (unsigned)(((kk * 2 + s0B) ^ l7) << 4);
                unsigned b0, b1, b2, b3;
                asm volatile("ldmatrix.sync.aligned.m8n8.x4.shared.b16 {%0,%1,%2,%3}, [%4];\n"
                             : "=r"(b0), "=r"(b1), "=r"(b2), "=r"(b3) : "r"(addrB));
                asm volatile("mma.sync.aligned.m16n8k16.row.col.f32.f16.f16.f32 "
                             "{%0,%1,%2,%3}, {%4,%5,%6,%7}, {%8,%9}, {%0,%1,%2,%3};\n"
                             : "+f"(acc[2*p][0]), "+f"(acc[2*p][1]),
                               "+f"(acc[2*p][2]), "+f"(acc[2*p][3])
                             : "r"(a0), "r"(a1), "r"(a2), "r"(a3), "r"(b0), "r"(b1));
                asm volatile("mma.sync.aligned.m16n8k16.row.col.f32.f16.f16.f32 "
                             "{%0,%1,%2,%3}, {%4,%5,%6,%7}, {%8,%9}, {%0,%1,%2,%3};\n"
                             : "+f"(acc[2*p+1][0]), "+f"(acc[2*p+1][1]),
                               "+f"(acc[2*p+1][2]), "+f"(acc[2*p+1][3])
                             : "r"(a0), "r"(a1), "r"(a2), "r"(a3), "r"(b2), "r"(b3));
            }
        }

        // Epilogue. acc[nt][h*2+j] = row (r0 + h*8), col n = nt*8 + cA + j.
        float partial[2] = {0.f, 0.f};
#pragma unroll
        for (int h = 0; h < 2; ++h) {
#pragma unroll
            for (int j = 0; j < 2; ++j) {
#pragma unroll
                for (int pp = 0; pp < 2; ++pp) {
                    float s = 0.f;
#pragma unroll
                    for (int q = 0; q < 4; ++q) {
                        int nt = 2 * q + pp;
                        int n = nt * 8 + cA + j;
                        float x = acc[nt][h * 2 + j] + sBias[n];
                        x = 1.0f / (1.0f + __expf(-x));
                        s = fmaf(x, sKern[n], s);
                    }
                    partial[h] += advq[h][pp * 2 + j] * (s - 1.0f);
                }
            }
        }
        partial[0] += __shfl_xor_sync(0xffffffffu, partial[0], 1);
        partial[0] += __shfl_xor_sync(0xffffffffu, partial[0], 2);
        partial[1] += __shfl_xor_sync(0xffffffffu, partial[1], 1);
        partial[1] += __shfl_xor_sync(0xffffffffu, partial[1], 2);
        if (qid == 0) {
            if (r0 < Btot) out[r0] = partial[0];
            if (r1 < Btot) out[r1] = partial[1];
        }

        if (!hasNext) break;
        tile = nextTile;
        gA0 = nA0; gA1 = nA1;
    }
}

// ---------------------------------------------------------------------------
extern "C" void kernel_launch(void* const* d_in, const int* in_sizes, int n_in,
                              void* d_out, int out_size)
{
    const float* agent_qs  = (const float*)d_in[0];
    const float* actions   = (const float*)d_in[1];
    const float* max_q_i   = (const float*)d_in[2];
    const float* selectors = (const float*)d_in[3];
    const float* keys      = (const float*)d_in[4];
    const float* V         = (const float*)d_in[5];
    const float* si_keys   = (const float*)d_in[6];
    const float* si_agents = (const float*)d_in[7];
    const float* si_W      = (const float*)d_in[8];
    const float* si_b      = (const float*)d_in[9];
    float* out = (float*)d_out;

    int Btot = in_sizes[0] / NA;   // B0*T

    cudaFuncSetAttribute(mixer_kernel,
                         cudaFuncAttributeMaxDynamicSharedMemorySize, SMEM_TOTAL);

    int ntiles = (Btot + MT - 1) / MT;
    int grid = ntiles < GRID ? ntiles : GRID;
    mixer_kernel<<<grid, NTHREADS, SMEM_TOTAL>>>(agent_qs, actions, max_q_i, V,
                                                 selectors, keys,
                                                 si_keys, si_agents, si_W, si_b,
                                                 out, Btot, out_size);
}

// round 17
// speedup vs baseline: 1.1695x; 1.0867x over previous
#include <cuda_runtime.h>
#include <cuda_fp16.h>

#define NA 16       // agents
#define ND 256      // action dim (K of the GEMM)
#define NN 64       // K_kernels * NA = output cols (N of the GEMM)
#define MT 256      // rows per tile (8 warps x 32)
#define NTHREADS 256
#define NWARPS 8
#define NSTAGES 5   // per-warp cp.async A stages (2KB each: 32 rows x 64B)
#define PIPE_D 4    // wait_group depth (max WAR-safe with 5 stages)
#define GRID 296    // 148 SMs x 2 CTAs: persistent
#define STAGE_B 2048

// dynamic smem layout (bytes)
#define SB_OFF    0                        // B tile fp16: 32KB
#define SA_OFF    32768                    // A ring: 8 warps * 5 stages * 2KB = 80KB
#define SKERN_OFF (32768 + NWARPS*NSTAGES*STAGE_B)
#define SBIAS_OFF (SKERN_OFF + 256)
#define SMEM_TOTAL (SBIAS_OFF + 256)       // 115200 -> 2 CTAs/SM

__device__ __forceinline__ unsigned pack_h2(float a, float b) {
    __half2 h = __floats2half2_rn(a, b);
    return *reinterpret_cast<unsigned*>(&h);
}

#define CP_ASYNC_CG16(dst_u32, src_ptr) \
    asm volatile("cp.async.cg.shared.global [%0], [%1], 16;\n" :: "r"(dst_u32), "l"(src_ptr))
#define CP_COMMIT()  asm volatile("cp.async.commit_group;\n" ::: "memory")
#define CP_WAIT()    asm volatile("cp.async.wait_group %0;\n" :: "n"(PIPE_D) : "memory")

// ---------------------------------------------------------------------------
// Persistent fused kernel, flattened cp.async pipeline (R12 slot form),
// 32 rows per warp: two m16 tiles share every ldmatrix'd B fragment,
// halving B shared-load traffic and per-row loop overhead.
// ---------------------------------------------------------------------------
__global__ void __launch_bounds__(NTHREADS, 2)
mixer_kernel(const float* __restrict__ aq,
             const float* __restrict__ acts,
             const float* __restrict__ mq,
             const float* __restrict__ Vp,
             const float* __restrict__ sel,
             const float* __restrict__ keysp,
             const float* __restrict__ si_keys,
             const float* __restrict__ si_agents,
             const float* __restrict__ si_W,
             const float* __restrict__ si_b,
             float* __restrict__ out,
             int Btot, int out_size)
{
    extern __shared__ char smem[];
    __half* sB    = reinterpret_cast<__half*>(smem + SB_OFF);
    float4* sA4   = reinterpret_cast<float4*>(smem + SA_OFF);
    float*  sKern = reinterpret_cast<float*>(smem + SKERN_OFF);
    float*  sBias = reinterpret_cast<float*>(smem + SBIAS_OFF);

    const int tid = threadIdx.x;

    // kern[n] = (|si_keys[k]|+1e-10) * sigmoid(si_agents[k][a]); bias[n] = si_b
    if (tid < NN) {
        int k = tid >> 4;
        float sg = 1.0f / (1.0f + __expf(-si_agents[tid]));
        sKern[tid] = (fabsf(si_keys[k]) + 1e-10f) * sg;
        sBias[tid] = si_b[tid];
    }

    // scalar tail outputs (one thread of one CTA)
    if (blockIdx.x == 0 && tid == NTHREADS - 1 && out_size >= Btot + 5) {
        float ssq = 0.f;
        for (int h = 0; h < 4; ++h) {
            float d = 0.f;
            for (int e = 0; e < 64; ++e) d = fmaf(sel[h * 64 + e], keysp[h * 64 + e], d);
            ssq += d * d;
        }
        out[Btot] = 0.001f * ssq;                  // attend_mag_regs
        float aw = 0.0625f;                         // softmax of equal logits
        float ent = -16.0f * (logf(aw + 1e-8f) * aw);
        for (int h = 0; h < 4; ++h) out[Btot + 1 + h] = ent;  // head_entropies
    }

    // Stage B ONCE from si_W: K-permutation fused into packing.
    // dest seg(2blk) = xy-halves of 4 float4s, seg(2blk+1) = zw-halves.
    // Swizzle: seg' = seg ^ (r & 7); 16B segments.
    for (int s = tid; s < 64 * 16; s += NTHREADS) {
        int r = s >> 4, blk = s & 15;
        const float4* src = reinterpret_cast<const float4*>(si_W + r * ND + blk * 16);
        float4 f0 = src[0], f1 = src[1], f2 = src[2], f3 = src[3];
        uint4 seg0, seg1;
        seg0.x = pack_h2(f0.x, f0.y); seg0.y = pack_h2(f1.x, f1.y);
        seg0.z = pack_h2(f2.x, f2.y); seg0.w = pack_h2(f3.x, f3.y);
        seg1.x = pack_h2(f0.z, f0.w); seg1.y = pack_h2(f1.z, f1.w);
        seg1.z = pack_h2(f2.z, f2.w); seg1.w = pack_h2(f3.z, f3.w);
        int c0 = 2 * blk, c1 = 2 * blk + 1;
        *reinterpret_cast<uint4*>(sB + r * ND + ((c0 ^ (r & 7)) << 3)) = seg0;
        *reinterpret_cast<uint4*>(sB + r * ND + ((c1 ^ (r & 7)) << 3)) = seg1;
    }
    __syncthreads();

    // warp-constant geometry
    const int w = tid >> 5, l = tid & 31;
    const int quad = l >> 2, qid = l & 3;
    const int l7 = l & 7, t8 = l >> 3;
    const int cA = qid * 2;
    const int ldRowA = l >> 2;            // cp.async: lane l owns 4 segments
    const int ldC4A  = l & 3;

    const unsigned sAaddr = (unsigned)__cvta_generic_to_shared(sA4) + (unsigned)(w * NSTAGES * STAGE_B);
    const unsigned sBaddr = (unsigned)__cvta_generic_to_shared(sB);
    // lane-private segment offsets within a 2KB stage: rows i*8+ldRowA, col ldC4A
    unsigned segOff[4];
#pragma unroll
    for (int i = 0; i < 4; ++i) segOff[i] = (unsigned)(((i * 8 + ldRowA) * 4 + ldC4A) * 16);
    const int rowB_off = (t8 >> 1) * 8 + l7;   // ldmatrix lane geometry
    const int s0B = t8 & 1;
    const float4* sAw = sA4 + w * NSTAGES * 128;  // this warp's ring base (128 f4/stage)

    const float v = Vp[0] * 0.0625f;
    const int ntiles = (Btot + MT - 1) / MT;

    int tile = blockIdx.x;
    if (tile >= ntiles) return;

    // per-tile A pointers (4 row-groups, clamped)
    const float* gA[4];
    {
        long wr0 = (long)tile * MT + w * 32;
#pragma unroll
        for (int i = 0; i < 4; ++i) {
            long g = wr0 + i * 8 + ldRowA;  if (g >= Btot) g = Btot - 1;
            gA[i] = acts + g * ND + ldC4A * 4;
        }
    }

    int ringOff = 0;   // ring slot of current tile's k-step 0 (global-iter mod 5)

    // prologue: first PIPE_D k-steps of the first tile (slots 0..3)
#pragma unroll
    for (int kk = 0; kk < PIPE_D; ++kk) {
        unsigned stBase = sAaddr + (unsigned)(kk * STAGE_B);
#pragma unroll
        for (int i = 0; i < 4; ++i) CP_ASYNC_CG16(stBase + segOff[i], gA[i] + kk * 16);
        CP_COMMIT();
    }

    while (true) {
        const int nextTile = tile + GRID;
        const bool hasNext = nextTile < ntiles;
        const float* nA[4];
#pragma unroll
        for (int i = 0; i < 4; ++i) nA[i] = gA[i];
        if (hasNext) {
            long wr0 = (long)nextTile * MT + w * 32;
#pragma unroll
            for (int i = 0; i < 4; ++i) {
                long g = wr0 + i * 8 + ldRowA;  if (g >= Btot) g = Btot - 1;
                nA[i] = acts + g * ND + ldC4A * 4;
            }
        }

        const long warpRow0 = (long)tile * MT + w * 32;

        float acc0[8][4], acc1[8][4];
#pragma unroll
        for (int i = 0; i < 8; ++i)
#pragma unroll
            for (int j = 0; j < 4; ++j) { acc0[i][j] = 0.f; acc1[i][j] = 0.f; }

#pragma unroll
        for (int kk = 0; kk < 16; ++kk) {
            // prefetch global-iteration (this + PIPE_D): same tile or next tile
            {
                int pre = kk + PIPE_D;
                int slot = (ringOff + pre) % NSTAGES;
                unsigned stBase = sAaddr + (unsigned)(slot * STAGE_B);
                if (pre < 16) {
#pragma unroll
                    for (int i = 0; i < 4; ++i)
                        CP_ASYNC_CG16(stBase + segOff[i], gA[i] + pre * 16);
                } else {
                    int pk = pre - 16;
#pragma unroll
                    for (int i = 0; i < 4; ++i)
                        CP_ASYNC_CG16(stBase + segOff[i], nA[i] + pk * 16);
                }
            }
            CP_COMMIT();
            CP_WAIT();        // groups <= PIPE_D outstanding -> iter kk complete

            int cslot = (ringOff + kk) % NSTAGES;
            const float4* st = sAw + cslot * 128;
            float4 f0 = st[quad * 4 + qid];            // m-tile 0, row quad
            float4 f1 = st[(quad + 8) * 4 + qid];      // m-tile 0, row quad+8
            float4 f2 = st[(quad + 16) * 4 + qid];     // m-tile 1, row quad
            float4 f3 = st[(quad + 24) * 4 + qid];     // m-tile 1, row quad+8
            unsigned a00 = pack_h2(f0.x, f0.y), a01 = pack_h2(f1.x, f1.y);
            unsigned a02 = pack_h2(f0.z, f0.w), a03 = pack_h2(f1.z, f1.w);
            unsigned a10 = pack_h2(f2.x, f2.y), a11 = pack_h2(f3.x, f3.y);
            unsigned a12 = pack_h2(f2.z, f2.w), a13 = pack_h2(f3.z, f3.w);
#pragma unroll
            for (int p = 0; p < 4; ++p) {
                unsigned addrB = sBaddr
                               + (unsigned)((p * 16 + rowB_off) * (ND * 2))
                               + (unsigned)(((kk * 2 + s0B) ^ l7) << 4);
                unsigned b0, b1, b2, b3;
                asm volatile("ldmatrix.sync.aligned.m8n8.x4.shared.b16 {%0,%1,%2,%3}, [%4];\n"
                             : "=r"(b0), "=r"(b1), "=r"(b2), "=r"(b3) : "r"(addrB));
                // m-tile 0
                asm volatile("mma.sync.aligned.m16n8k16.row.col.f32.f16.f16.f32 "
                             "{%0,%1,%2,%3}, {%4,%5,%6,%7}, {%8,%9}, {%0,%1,%2,%3};\n"
                             : "+f"(acc0[2*p][0]), "+f"(acc0[2*p][1]),
                               "+f"(acc0[2*p][2]), "+f"(acc0[2*p][3])
                             : "r"(a00), "r"(a01), "r"(a02), "r"(a03), "r"(b0), "r"(b1));
                asm volatile("mma.sync.aligned.m16n8k16.row.col.f32.f16.f16.f32 "
                             "{%0,%1,%2,%3}, {%4,%5,%6,%7}, {%8,%9}, {%0,%1,%2,%3};\n"
                             : "+f"(acc0[2*p+1][0]), "+f"(acc0[2*p+1][1]),
                               "+f"(acc0[2*p+1][2]), "+f"(acc0[2*p+1][3])
                             : "r"(a00), "r"(a01), "r"(a02), "r"(a03), "r"(b2), "r"(b3));
                // m-tile 1 (same B fragments)
                asm volatile("mma.sync.aligned.m16n8k16.row.col.f32.f16.f16.f32 "
                             "{%0,%1,%2,%3}, {%4,%5,%6,%7}, {%8,%9}, {%0,%1,%2,%3};\n"
                             : "+f"(acc1[2*p][0]), "+f"(acc1[2*p][1]),
                               "+f"(acc1[2*p][2]), "+f"(acc1[2*p][3])
                             : "r"(a10), "r"(a11), "r"(a12), "r"(a13), "r"(b0), "r"(b1));
                asm volatile("mma.sync.aligned.m16n8k16.row.col.f32.f16.f16.f32 "
                             "{%0,%1,%2,%3}, {%4,%5,%6,%7}, {%8,%9}, {%0,%1,%2,%3};\n"
                             : "+f"(acc1[2*p+1][0]), "+f"(acc1[2*p+1][1]),
                               "+f"(acc1[2*p+1][2]), "+f"(acc1[2*p+1][3])
                             : "r"(a10), "r"(a11), "r"(a12), "r"(a13), "r"(b2), "r"(b3));
            }
        }

        // Epilogue per m-tile. accT[nt][h*2+j] = row (rT + h*8), col n = nt*8+cA+j.
#pragma unroll
        for (int t = 0; t < 2; ++t) {
            long r0 = warpRow0 + t * 16 + quad;
            long r1 = r0 + 8;
            long r0c = (r0 < Btot) ? r0 : (long)(Btot - 1);
            long r1c = (r1 < Btot) ? r1 : (long)(Btot - 1);
            const float* aqr0 = aq + r0c * NA;
            const float* aqr1 = aq + r1c * NA;
            const float* mqr0 = mq + r0c * NA;
            const float* mqr1 = mq + r1c * NA;
            float2 aq0a = __ldcs((const float2*)(aqr0 + cA));
            float2 aq0b = __ldcs((const float2*)(aqr0 + cA + 8));
            float2 aq1a = __ldcs((const float2*)(aqr1 + cA));
            float2 aq1b = __ldcs((const float2*)(aqr1 + cA + 8));
            float2 mq0a = __ldcs((const float2*)(mqr0 + cA));
            float2 mq0b = __ldcs((const float2*)(mqr0 + cA + 8));
            float2 mq1a = __ldcs((const float2*)(mqr1 + cA));
            float2 mq1b = __ldcs((const float2*)(mqr1 + cA + 8));
            float advq[2][4];
            advq[0][0] = fmaf(0.25f, aq0a.x, v) - fmaf(0.25f, mq0a.x, v);
            advq[0][1] = fmaf(0.25f, aq0a.y, v) - fmaf(0.25f, mq0a.y, v);
            advq[0][2] = fmaf(0.25f, aq0b.x, v) - fmaf(0.25f, mq0b.x, v);
            advq[0][3] = fmaf(0.25f, aq0b.y, v) - fmaf(0.25f, mq0b.y, v);
            advq[1][0] = fmaf(0.25f, aq1a.x, v) - fmaf(0.25f, mq1a.x, v);
            advq[1][1] = fmaf(0.25f, aq1a.y, v) - fmaf(0.25f, mq1a.y, v);
            advq[1][2] = fmaf(0.25f, aq1b.x, v) - fmaf(0.25f, mq1b.x, v);
            advq[1][3] = fmaf(0.25f, aq1b.y, v) - fmaf(0.25f, mq1b.y, v);

            float partial[2] = {0.f, 0.f};
#pragma unroll
            for (int h = 0; h < 2; ++h) {
#pragma unroll
                for (int j = 0; j < 2; ++j) {
#pragma unroll
                    for (int pp = 0; pp < 2; ++pp) {
                        float s = 0.f;
#pragma unroll
                        for (int q = 0; q < 4; ++q) {
                            int nt = 2 * q + pp;
                            int n = nt * 8 + cA + j;
                            float x = (t == 0 ? acc0[nt][h * 2 + j] : acc1[nt][h * 2 + j]) + sBias[n];
                            x = 1.0f / (1.0f + __expf(-x));
                            s = fmaf(x, sKern[n], s);
                        }
                        partial[h] += advq[h][pp * 2 + j] * (s - 1.0f);
                    }
                }
            }
            partial[0] += __shfl_xor_sync(0xffffffffu, partial[0], 1);
            partial[0] += __shfl_xor_sync(0xffffffffu, partial[0], 2);
            partial[1] += __shfl_xor_sync(0xffffffffu, partial[1], 1);
            partial[1] += __shfl_xor_sync(0xffffffffu, partial[1], 2);
            if (qid == 0) {
                if (r0 < Btot) out[r0] = partial[0];
                if (r1 < Btot) out[r1] = partial[1];
            }
        }

        if (!hasNext) break;
        tile = nextTile;
#pragma unroll
        for (int i = 0; i < 4; ++i) gA[i] = nA[i];
        ringOff += 1;                         // 16 mod 5
        if (ringOff >= NSTAGES) ringOff -= NSTAGES;
    }
}

// ---------------------------------------------------------------------------
extern "C" void kernel_launch(void* const* d_in, const int* in_sizes, int n_in,
                              void* d_out, int out_size)
{
    const float* agent_qs  = (const float*)d_in[0];
    const float* actions   = (const float*)d_in[1];
    const float* max_q_i   = (const float*)d_in[2];
    const float* selectors = (const float*)d_in[3];
    const float* keys      = (const float*)d_in[4];
    const float* V         = (const float*)d_in[5];
    const float* si_keys   = (const float*)d_in[6];
    const float* si_agents = (const float*)d_in[7];
    const float* si_W      = (const float*)d_in[8];
    const float* si_b      = (const float*)d_in[9];
    float* out = (float*)d_out;

    int Btot = in_sizes[0] / NA;   // B0*T

    cudaFuncSetAttribute(mixer_kernel,
                         cudaFuncAttributeMaxDynamicSharedMemorySize, SMEM_TOTAL);

    int ntiles = (Btot + MT - 1) / MT;
    int grid = ntiles < GRID ? ntiles : GRID;
    mixer_kernel<<<grid, NTHREADS, SMEM_TOTAL>>>(agent_qs, actions, max_q_i, V,
                                                 selectors, keys,
                                                 si_keys, si_agents, si_W, si_b,
                                                 out, Btot, out_size);
}